// round 3
// baseline (speedup 1.0000x reference)
#include <cuda_runtime.h>
#include <math.h>
#include <stdint.h>

#define NSRC   2048
#define NGRID  50000
#define NLOCS  500
#define KTOP   5
#define NSLICE 32
#define SL     1563   // ceil(NGRID / NSLICE); last slice = 1547

// ---------------- device scratch (no allocations allowed) ----------------
__device__ float4 g_gpk[NGRID];                 // (gx,gy,gz,|g|^2), scaled /1000
__device__ float4 g_spk[NSRC];                  // (sx,sy,sz,|s|^2), scaled /1000
__device__ float  g_pd[NSRC * NSLICE * KTOP];   // partial top-5 d2 per (src, slice)
__device__ int    g_pi[NSRC * NSLICE * KTOP];   // partial top-5 grid idx
__device__ int    g_topk[NSRC * KTOP];          // final top-5 grid idx per src

// ---------------- kernel 0: pack grid & src into float4 ------------------
__global__ void pack_kernel(const float* __restrict__ src,
                            const float* __restrict__ grid) {
    int i = blockIdx.x * blockDim.x + threadIdx.x;
    if (i < NGRID) {
        float x = grid[i * 3 + 0] / 1000.0f;
        float y = grid[i * 3 + 1] / 1000.0f;
        float z = grid[i * 3 + 2] / 1000.0f;
        float n2 = __fadd_rn(__fadd_rn(__fmul_rn(x, x), __fmul_rn(y, y)),
                             __fmul_rn(z, z));
        g_gpk[i] = make_float4(x, y, z, n2);
    }
    if (i < NSRC) {
        float x = src[i * 3 + 0] / 1000.0f;
        float y = src[i * 3 + 1] / 1000.0f;
        float z = src[i * 3 + 2] / 1000.0f;
        float n2 = __fadd_rn(__fadd_rn(__fmul_rn(x, x), __fmul_rn(y, y)),
                             __fmul_rn(z, z));
        g_spk[i] = make_float4(x, y, z, n2);
    }
}

// ---------------- kernel 1: per-(src, slice) top-5 -----------------------
// grid = (8, 32): blockIdx.x = source chunk of 256, blockIdx.y = grid slice.
// 256 threads; lane -> source (32 sources per warp); tile[j] read is uniform
// per warp -> LDS broadcast (conflict-free, N=1).
__global__ __launch_bounds__(256, 4)
void topk_slice_kernel() {
    __shared__ float4 tile[SL];

    const int slice = blockIdx.y;
    const int base  = slice * SL;
    const int n     = min(SL, NGRID - base);

    for (int k = threadIdx.x; k < n; k += blockDim.x)
        tile[k] = g_gpk[base + k];
    __syncthreads();

    const int s = blockIdx.x * 256 + threadIdx.x;   // source index
    const float4 sp = g_spk[s];
    const float sx = sp.x, sy = sp.y, sz = sp.z, s2 = sp.w;

    const float INF = __int_as_float(0x7f800000);
    float t0 = INF, t1 = INF, t2 = INF, t3 = INF, t4 = INF;
    int   i0 = 0x7fffffff, i1 = 0x7fffffff, i2 = 0x7fffffff,
          i3 = 0x7fffffff, i4 = 0x7fffffff;

#pragma unroll 4
    for (int j = 0; j < n; j++) {
        float4 g = tile[j];
        // match reference: d2 = (s2 + g2) - 2*(s . g)
        float dot = fmaf(sz, g.z, fmaf(sy, g.y, __fmul_rn(sx, g.x)));
        float d2  = __fadd_rn(__fadd_rn(s2, g.w), -__fmul_rn(2.0f, dot));
        if (d2 < t4) {
            int idx = base + j;
            if (d2 < t3) {
                t4 = t3; i4 = i3;
                if (d2 < t2) {
                    t3 = t2; i3 = i2;
                    if (d2 < t1) {
                        t2 = t1; i2 = i1;
                        if (d2 < t0) {
                            t1 = t0; i1 = i0; t0 = d2; i0 = idx;
                        } else { t1 = d2; i1 = idx; }
                    } else { t2 = d2; i2 = idx; }
                } else { t3 = d2; i3 = idx; }
            } else { t4 = d2; i4 = idx; }
        }
    }

    const int o = (s * NSLICE + slice) * KTOP;
    g_pd[o + 0] = t0; g_pi[o + 0] = i0;
    g_pd[o + 1] = t1; g_pi[o + 1] = i1;
    g_pd[o + 2] = t2; g_pi[o + 2] = i2;
    g_pd[o + 3] = t3; g_pi[o + 3] = i3;
    g_pd[o + 4] = t4; g_pi[o + 4] = i4;
}

// ---------------- kernel 2: merge 32 slices x 5 -> top-5 per src ----------
// One warp per source; lane = slice (NSLICE == 32). Each lane holds its
// slice's sorted 5 candidates; 5 rounds of warp-min with index tie-break.
__global__ void topk_merge_kernel() {
    const int warp = (blockIdx.x * blockDim.x + threadIdx.x) >> 5;
    const int lane = threadIdx.x & 31;
    if (warp >= NSRC) return;
    const int src = warp;

    const int o = (src * NSLICE + lane) * KTOP;
    float c0 = g_pd[o + 0], c1 = g_pd[o + 1], c2 = g_pd[o + 2],
          c3 = g_pd[o + 3], c4 = g_pd[o + 4];
    int   j0 = g_pi[o + 0], j1 = g_pi[o + 1], j2 = g_pi[o + 2],
          j3 = g_pi[o + 3], j4 = g_pi[o + 4];

    const float INF = __int_as_float(0x7f800000);

#pragma unroll
    for (int r = 0; r < KTOP; r++) {
        float bv = c0; int bi = j0;
#pragma unroll
        for (int off = 16; off > 0; off >>= 1) {
            float ov = __shfl_xor_sync(0xffffffffu, bv, off);
            int   oi = __shfl_xor_sync(0xffffffffu, bi, off);
            if (ov < bv || (ov == bv && oi < bi)) { bv = ov; bi = oi; }
        }
        if (lane == 0) g_topk[src * KTOP + r] = bi;
        if (c0 == bv && j0 == bi) {   // winner lane advances (indices unique)
            c0 = c1; j0 = j1; c1 = c2; j1 = j2;
            c2 = c3; j2 = j3; c3 = c4; j3 = j4;
            c4 = INF; j4 = 0x7fffffff;
        }
    }
}

// ---------------- kernel 3: fused epilogue --------------------------------
// block = one source row (512 threads, 500 active); gathers 5 bias rows
// (L1/L2 resident), computes log-distance terms, writes mag.
__global__ __launch_bounds__(512)
void final_kernel(const float* __restrict__ src,
                  const int*   __restrict__ ind,
                  const float* __restrict__ log_amp,
                  const int*   __restrict__ phase,
                  const float* __restrict__ locs,
                  const float* __restrict__ mag_coef,
                  const float* __restrict__ eps_coef,
                  const float* __restrict__ dep_coef,
                  const float* __restrict__ bias,
                  float*       __restrict__ out) {
    const int s = blockIdx.x;
    const int l = threadIdx.x;

    __shared__ int tk[KTOP];
    if (threadIdx.x < KTOP) tk[threadIdx.x] = g_topk[s * KTOP + threadIdx.x];
    __syncthreads();

    if (l >= NLOCS) return;

    const int ph = phase[0];
    const float ec = eps_coef[ph];
    const float dc = dep_coef[ph];
    const float denom = fmaxf(mag_coef[ph], 1e-12f);

    const float sx = src[s * 3 + 0];
    const float sy = src[s * 3 + 1];
    const float sz = src[s * 3 + 2];

    const int li = ind[l];
    const float lx = locs[li * 3 + 0];
    const float ly = locs[li * 3 + 1];
    const float lz = locs[li * 3 + 2];

    const float dx = sx - lx;
    const float dy = sy - ly;
    const float d0 = sqrtf(__fadd_rn(__fmul_rn(dx, dx), __fmul_rn(dy, dy)));
    const float ld0 = log10f(d0 + 1.0f);
    const float ldd = log10f(fabsf(sz - lz) + 1.0f);

    float b = 0.0f;
#pragma unroll
    for (int k = 0; k < KTOP; k++)
        b += bias[tk[k] * (NLOCS * 2) + li * 2 + ph];
    b = b / 5.0f;

    const float la = log_amp[s * NLOCS + l];
    out[s * NLOCS + l] = (la - ec * ld0 - dc * ldd - b) / denom;
}

// ---------------- launch ---------------------------------------------------
extern "C" void kernel_launch(void* const* d_in, const int* in_sizes, int n_in,
                              void* d_out, int out_size) {
    const float* src      = (const float*)d_in[0];
    const int*   ind      = (const int*)  d_in[1];
    const float* log_amp  = (const float*)d_in[2];
    const int*   phase    = (const int*)  d_in[3];
    const float* locs     = (const float*)d_in[4];
    const float* grid     = (const float*)d_in[5];
    const float* mag_coef = (const float*)d_in[6];
    const float* eps_coef = (const float*)d_in[7];
    const float* dep_coef = (const float*)d_in[8];
    const float* bias     = (const float*)d_in[9];
    float* out = (float*)d_out;

    // kernel 0: pack grid + src
    pack_kernel<<<(NGRID + 255) / 256, 256>>>(src, grid);

    // kernel 1: sliced top-5 (8 source-chunks x 32 slices)
    dim3 g1(NSRC / 256, NSLICE);
    topk_slice_kernel<<<g1, 256>>>();

    // kernel 2: merge partials (2048 warps)
    topk_merge_kernel<<<(NSRC * 32 + 255) / 256, 256>>>();

    // kernel 3: fused epilogue
    final_kernel<<<NSRC, 512>>>(src, ind, log_amp, phase, locs,
                                mag_coef, eps_coef, dep_coef, bias, out);
}

// round 4
// speedup vs baseline: 1.1373x; 1.1373x over previous
#include <cuda_runtime.h>
#include <math.h>
#include <stdint.h>

#define NSRC   2048
#define NGRID  50000
#define NLOCS  500
#define KTOP   5
#define NSLICE 64
#define SL     782    // ceil(NGRID / NSLICE); last slice = 734

// ---------------- device scratch (no allocations allowed) ----------------
__device__ float g_pd[NSRC * NSLICE * KTOP];   // partial top-5 "e" per (src, slice)
__device__ int   g_pi[NSRC * NSLICE * KTOP];   // partial top-5 grid idx

// ---------------- kernel 1: per-(src, slice) top-5 -----------------------
// grid = (8, 64): blockIdx.x = source chunk of 256, blockIdx.y = grid slice.
// 256 threads; lane -> source (32 sources per warp); tile[j] read is a
// uniform warp address -> LDS broadcast (conflict-free).
// Ordering key: e = gw - 2*s.g  (== d2 - s2; s2 constant per source, so
// same ordering as the reference d2 up to near-tie rounding).
__global__ __launch_bounds__(256, 6)
void topk_slice_kernel(const float* __restrict__ src,
                       const float* __restrict__ grid) {
    __shared__ float4 tile[SL];

    const int slice = blockIdx.y;
    const int base  = slice * SL;
    const int n     = min(SL, NGRID - base);

    // fused pack: raw grid -> scaled coords + squared norm
    for (int k = threadIdx.x; k < n; k += 256) {
        float x = grid[(base + k) * 3 + 0] / 1000.0f;
        float y = grid[(base + k) * 3 + 1] / 1000.0f;
        float z = grid[(base + k) * 3 + 2] / 1000.0f;
        float n2 = __fadd_rn(__fadd_rn(__fmul_rn(x, x), __fmul_rn(y, y)),
                             __fmul_rn(z, z));
        tile[k] = make_float4(x, y, z, n2);
    }
    __syncthreads();

    const int s = blockIdx.x * 256 + threadIdx.x;   // source index
    const float sx = src[s * 3 + 0] / 1000.0f;
    const float sy = src[s * 3 + 1] / 1000.0f;
    const float sz = src[s * 3 + 2] / 1000.0f;
    const float mx = -2.0f * sx, my = -2.0f * sy, mz = -2.0f * sz;

    const float INF = __int_as_float(0x7f800000);
    float t0 = INF, t1 = INF, t2 = INF, t3 = INF, t4 = INF;
    int   i0 = 0x7fffffff, i1 = 0x7fffffff, i2 = 0x7fffffff,
          i3 = 0x7fffffff, i4 = 0x7fffffff;

#pragma unroll 4
    for (int j = 0; j < n; j++) {
        float4 g = tile[j];
        float e = fmaf(mx, g.x, fmaf(my, g.y, fmaf(mz, g.z, g.w)));
        if (e < t4) {
            int idx = base + j;
            if (e < t3) {
                t4 = t3; i4 = i3;
                if (e < t2) {
                    t3 = t2; i3 = i2;
                    if (e < t1) {
                        t2 = t1; i2 = i1;
                        if (e < t0) {
                            t1 = t0; i1 = i0; t0 = e; i0 = idx;
                        } else { t1 = e; i1 = idx; }
                    } else { t2 = e; i2 = idx; }
                } else { t3 = e; i3 = idx; }
            } else { t4 = e; i4 = idx; }
        }
    }

    const int o = (s * NSLICE + slice) * KTOP;
    g_pd[o + 0] = t0; g_pi[o + 0] = i0;
    g_pd[o + 1] = t1; g_pi[o + 1] = i1;
    g_pd[o + 2] = t2; g_pi[o + 2] = i2;
    g_pd[o + 3] = t3; g_pi[o + 3] = i3;
    g_pd[o + 4] = t4; g_pi[o + 4] = i4;
}

// ---------------- kernel 2: fused merge + bias rowsum + epilogue -----------
// One block per source (512 threads).
//   stage A (warp 0): merge 64 slices x 5 -> top-5 grid indices.
//                     lane owns slices (lane) and (lane+32) as two sorted
//                     head-lists; 5 rounds of warp-min with index tie-break.
//   stage B: threads 0..499 stream the 5 selected bias rows as coalesced
//            float2 and reduce into shared bsum[500].
//   stage C: per-station epilogue (log distances + affine), coalesced write.
__global__ __launch_bounds__(512)
void final_kernel(const float* __restrict__ src,
                  const int*   __restrict__ ind,
                  const float* __restrict__ log_amp,
                  const int*   __restrict__ phase,
                  const float* __restrict__ locs,
                  const float* __restrict__ mag_coef,
                  const float* __restrict__ eps_coef,
                  const float* __restrict__ dep_coef,
                  const float* __restrict__ bias,
                  float*       __restrict__ out) {
    const int s   = blockIdx.x;
    const int tid = threadIdx.x;

    __shared__ int   tk[KTOP];
    __shared__ float bsum[NLOCS];

    if (tid < 32) {
        const int lane = tid;
        const float INF = __int_as_float(0x7f800000);

        int oa = (s * NSLICE + lane) * KTOP;
        int ob = (s * NSLICE + 32 + lane) * KTOP;
        float a0 = g_pd[oa+0], a1 = g_pd[oa+1], a2 = g_pd[oa+2],
              a3 = g_pd[oa+3], a4 = g_pd[oa+4];
        int   ja0 = g_pi[oa+0], ja1 = g_pi[oa+1], ja2 = g_pi[oa+2],
              ja3 = g_pi[oa+3], ja4 = g_pi[oa+4];
        float b0 = g_pd[ob+0], b1 = g_pd[ob+1], b2 = g_pd[ob+2],
              b3 = g_pd[ob+3], b4 = g_pd[ob+4];
        int   jb0 = g_pi[ob+0], jb1 = g_pi[ob+1], jb2 = g_pi[ob+2],
              jb3 = g_pi[ob+3], jb4 = g_pi[ob+4];

#pragma unroll
        for (int r = 0; r < KTOP; r++) {
            bool pickA = (a0 < b0) || (a0 == b0 && ja0 < jb0);
            float lv = pickA ? a0 : b0;
            int   li = pickA ? ja0 : jb0;

            float bv = lv; int bi = li;
#pragma unroll
            for (int off = 16; off > 0; off >>= 1) {
                float ov = __shfl_xor_sync(0xffffffffu, bv, off);
                int   oi = __shfl_xor_sync(0xffffffffu, bi, off);
                if (ov < bv || (ov == bv && oi < bi)) { bv = ov; bi = oi; }
            }
            if (lane == 0) tk[r] = bi;
            if (lv == bv && li == bi) {          // this lane's head won
                if (pickA) {
                    a0 = a1; ja0 = ja1; a1 = a2; ja1 = ja2;
                    a2 = a3; ja2 = ja3; a3 = a4; ja3 = ja4;
                    a4 = INF; ja4 = 0x7fffffff;
                } else {
                    b0 = b1; jb0 = jb1; b1 = b2; jb1 = jb2;
                    b2 = b3; jb2 = jb3; b3 = b4; jb3 = jb4;
                    b4 = INF; jb4 = 0x7fffffff;
                }
            }
        }
    }
    __syncthreads();

    const int ph = phase[0];

    // stage B: coalesced float2 reads of the 5 selected bias rows
    if (tid < NLOCS) {
        float acc = 0.0f;
#pragma unroll
        for (int k = 0; k < KTOP; k++) {
            const float2* row =
                (const float2*)(bias + (size_t)tk[k] * (NLOCS * 2));
            float2 v = __ldg(&row[tid]);
            acc += ph ? v.y : v.x;
        }
        bsum[tid] = acc / 5.0f;
    }
    __syncthreads();

    if (tid >= NLOCS) return;

    const float ec    = eps_coef[ph];
    const float dc    = dep_coef[ph];
    const float denom = fmaxf(mag_coef[ph], 1e-12f);

    const float sx = src[s * 3 + 0];
    const float sy = src[s * 3 + 1];
    const float sz = src[s * 3 + 2];

    const int li = ind[tid];
    const float lx = locs[li * 3 + 0];
    const float ly = locs[li * 3 + 1];
    const float lz = locs[li * 3 + 2];

    const float dx = sx - lx;
    const float dy = sy - ly;
    const float d0  = sqrtf(__fadd_rn(__fmul_rn(dx, dx), __fmul_rn(dy, dy)));
    const float ld0 = log10f(d0 + 1.0f);
    const float ldd = log10f(fabsf(sz - lz) + 1.0f);

    const float b  = bsum[li];
    const float la = log_amp[s * NLOCS + tid];
    out[s * NLOCS + tid] = (la - ec * ld0 - dc * ldd - b) / denom;
}

// ---------------- launch ---------------------------------------------------
extern "C" void kernel_launch(void* const* d_in, const int* in_sizes, int n_in,
                              void* d_out, int out_size) {
    const float* src      = (const float*)d_in[0];
    const int*   ind      = (const int*)  d_in[1];
    const float* log_amp  = (const float*)d_in[2];
    const int*   phase    = (const int*)  d_in[3];
    const float* locs     = (const float*)d_in[4];
    const float* grid     = (const float*)d_in[5];
    const float* mag_coef = (const float*)d_in[6];
    const float* eps_coef = (const float*)d_in[7];
    const float* dep_coef = (const float*)d_in[8];
    const float* bias     = (const float*)d_in[9];
    float* out = (float*)d_out;

    dim3 g1(NSRC / 256, NSLICE);
    topk_slice_kernel<<<g1, 256>>>(src, grid);

    final_kernel<<<NSRC, 512>>>(src, ind, log_amp, phase, locs,
                                mag_coef, eps_coef, dep_coef, bias, out);
}

// round 5
// speedup vs baseline: 1.9560x; 1.7199x over previous
#include <cuda_runtime.h>
#include <math.h>
#include <stdint.h>

#define NSRC   2048
#define NGRID  50000
#define NLOCS  500
#define KTOP   5
#define NSLICE 256
#define SL     196          // ceil(50000/256); last slice has 20 points
#define FINF   __int_as_float(0x7f800000)

// ---------------- device scratch ----------------
__device__ float g_sd[NSRC * NSLICE];      // per (src, slice) min "e"
__device__ int   g_topk[NSRC * KTOP];      // final top-5 grid idx per src

// ============ kernel 1: per-(src, slice) branchless minimum ============
// grid = (NSRC/256, NSLICE); 256 threads; lane -> source.
// Ordering key: e = |g|^2 - 2*s.g  (== d2 - |s|^2, same order as ref d2).
__global__ __launch_bounds__(256)
void slice_min_kernel(const float* __restrict__ src,
                      const float* __restrict__ grid) {
    __shared__ float4 tile[SL];

    const int slice = blockIdx.y;
    const int base  = slice * SL;
    const int n     = min(SL, NGRID - base);

    if (threadIdx.x < n) {
        int gi = base + threadIdx.x;
        float x = grid[gi * 3 + 0] / 1000.0f;
        float y = grid[gi * 3 + 1] / 1000.0f;
        float z = grid[gi * 3 + 2] / 1000.0f;
        float n2 = __fadd_rn(__fadd_rn(__fmul_rn(x, x), __fmul_rn(y, y)),
                             __fmul_rn(z, z));
        tile[threadIdx.x] = make_float4(x, y, z, n2);
    }
    __syncthreads();

    const int s = blockIdx.x * 256 + threadIdx.x;
    const float mx = -2.0f * (src[s * 3 + 0] / 1000.0f);
    const float my = -2.0f * (src[s * 3 + 1] / 1000.0f);
    const float mz = -2.0f * (src[s * 3 + 2] / 1000.0f);

    float m0 = FINF, m1 = FINF, m2 = FINF, m3 = FINF;
    int j = 0;
    for (; j + 4 <= n; j += 4) {
        float4 a = tile[j + 0];
        float4 b = tile[j + 1];
        float4 c = tile[j + 2];
        float4 d = tile[j + 3];
        m0 = fminf(m0, fmaf(mx, a.x, fmaf(my, a.y, fmaf(mz, a.z, a.w))));
        m1 = fminf(m1, fmaf(mx, b.x, fmaf(my, b.y, fmaf(mz, b.z, b.w))));
        m2 = fminf(m2, fmaf(mx, c.x, fmaf(my, c.y, fmaf(mz, c.z, c.w))));
        m3 = fminf(m3, fmaf(mx, d.x, fmaf(my, d.y, fmaf(mz, d.z, d.w))));
    }
    for (; j < n; j++) {
        float4 a = tile[j];
        m0 = fminf(m0, fmaf(mx, a.x, fmaf(my, a.y, fmaf(mz, a.z, a.w))));
    }
    g_sd[s * NSLICE + slice] = fminf(fminf(m0, m1), fminf(m2, m3));
}

// ============ kernel 2: exact top-5 per source ============
// block = one source, 256 threads.
//  A) 5 rounds of block-argmin over 256 slice minima -> 5 candidate slices
//     (provably contain the global top-5).
//  B) recompute e for the <=980 candidate points into smem.
//  C) 5 rounds of block-argmin with grid-index tie-break -> g_topk.
__global__ __launch_bounds__(256)
void select_kernel(const float* __restrict__ src,
                   const float* __restrict__ grid) {
    const int s = blockIdx.x;
    const int t = threadIdx.x;
    const int lane = t & 31;
    const int wid  = t >> 5;

    __shared__ float sv[NSLICE];
    __shared__ int   csl[KTOP];
    __shared__ float ev[KTOP * SL];
    __shared__ int   eg[KTOP * SL];
    __shared__ float wv[8];
    __shared__ int   wj[8];
    __shared__ int   win_g;

    sv[t] = g_sd[s * NSLICE + t];
    __syncthreads();

    // ---- stage A: 5 smallest slice minima (tie -> lower slice id) ----
    for (int r = 0; r < KTOP; r++) {
        float v = sv[t];
        int   j = t;
#pragma unroll
        for (int off = 16; off > 0; off >>= 1) {
            float ov = __shfl_xor_sync(0xffffffffu, v, off);
            int   oj = __shfl_xor_sync(0xffffffffu, j, off);
            if (ov < v || (ov == v && oj < j)) { v = ov; j = oj; }
        }
        if (lane == 0) { wv[wid] = v; wj[wid] = j; }
        __syncthreads();
        if (t < 8) {
            float v2 = wv[t];
            int   j2 = wj[t];
#pragma unroll
            for (int off = 4; off > 0; off >>= 1) {
                float ov = __shfl_xor_sync(0x000000ffu, v2, off);
                int   oj = __shfl_xor_sync(0x000000ffu, j2, off);
                if (ov < v2 || (ov == v2 && oj < j2)) { v2 = ov; j2 = oj; }
            }
            if (t == 0) { csl[r] = j2; sv[j2] = FINF; }
        }
        __syncthreads();
    }

    // ---- stage B: candidate e values ----
    const float mx = -2.0f * (src[s * 3 + 0] / 1000.0f);
    const float my = -2.0f * (src[s * 3 + 1] / 1000.0f);
    const float mz = -2.0f * (src[s * 3 + 2] / 1000.0f);

    if (t < SL) {
#pragma unroll
        for (int k = 0; k < KTOP; k++) {
            int gi = csl[k] * SL + t;
            float e = FINF;
            if (gi < NGRID) {
                float x = grid[gi * 3 + 0] / 1000.0f;
                float y = grid[gi * 3 + 1] / 1000.0f;
                float z = grid[gi * 3 + 2] / 1000.0f;
                float n2 = __fadd_rn(__fadd_rn(__fmul_rn(x, x),
                                               __fmul_rn(y, y)),
                                     __fmul_rn(z, z));
                e = fmaf(mx, x, fmaf(my, y, fmaf(mz, z, n2)));
            }
            ev[k * SL + t] = e;
            eg[k * SL + t] = gi;
        }
    }
    __syncthreads();

    // ---- stage C: 5 rounds argmin over 980 (tie -> lower grid idx) ----
    const int TOT = KTOP * SL;
    for (int r = 0; r < KTOP; r++) {
        float bv = FINF;
        int   bg = 0x7fffffff;
        for (int p = t; p < TOT; p += 256) {
            float v = ev[p];
            int   g = eg[p];
            if (v < bv || (v == bv && g < bg)) { bv = v; bg = g; }
        }
#pragma unroll
        for (int off = 16; off > 0; off >>= 1) {
            float ov = __shfl_xor_sync(0xffffffffu, bv, off);
            int   og = __shfl_xor_sync(0xffffffffu, bg, off);
            if (ov < bv || (ov == bv && og < bg)) { bv = ov; bg = og; }
        }
        if (lane == 0) { wv[wid] = bv; wj[wid] = bg; }
        __syncthreads();
        if (t < 8) {
            float v2 = wv[t];
            int   g2 = wj[t];
#pragma unroll
            for (int off = 4; off > 0; off >>= 1) {
                float ov = __shfl_xor_sync(0x000000ffu, v2, off);
                int   og = __shfl_xor_sync(0x000000ffu, g2, off);
                if (ov < v2 || (ov == v2 && og < g2)) { v2 = ov; g2 = og; }
            }
            if (t == 0) { g_topk[s * KTOP + r] = g2; win_g = g2; }
        }
        __syncthreads();
        for (int p = t; p < TOT; p += 256)
            if (eg[p] == win_g) ev[p] = FINF;   // grid idx unique across slices
        __syncthreads();
    }
}

// ============ kernel 3: bias rowsum + epilogue ============
__global__ __launch_bounds__(512)
void final_kernel(const float* __restrict__ src,
                  const int*   __restrict__ ind,
                  const float* __restrict__ log_amp,
                  const int*   __restrict__ phase,
                  const float* __restrict__ locs,
                  const float* __restrict__ mag_coef,
                  const float* __restrict__ eps_coef,
                  const float* __restrict__ dep_coef,
                  const float* __restrict__ bias,
                  float*       __restrict__ out) {
    const int s   = blockIdx.x;
    const int tid = threadIdx.x;

    __shared__ int   tk[KTOP];
    __shared__ float bsum[NLOCS];

    if (tid < KTOP) tk[tid] = g_topk[s * KTOP + tid];
    __syncthreads();

    const int ph = phase[0];

    if (tid < NLOCS) {
        float acc = 0.0f;
#pragma unroll
        for (int k = 0; k < KTOP; k++) {
            const float2* row =
                (const float2*)(bias + (size_t)tk[k] * (NLOCS * 2));
            float2 v = __ldg(&row[tid]);
            acc += ph ? v.y : v.x;
        }
        bsum[tid] = acc / 5.0f;
    }
    __syncthreads();

    if (tid >= NLOCS) return;

    const float ec    = eps_coef[ph];
    const float dc    = dep_coef[ph];
    const float denom = fmaxf(mag_coef[ph], 1e-12f);

    const float sx = src[s * 3 + 0];
    const float sy = src[s * 3 + 1];
    const float sz = src[s * 3 + 2];

    const int li = ind[tid];
    const float lx = locs[li * 3 + 0];
    const float ly = locs[li * 3 + 1];
    const float lz = locs[li * 3 + 2];

    const float dx = sx - lx;
    const float dy = sy - ly;
    const float d0  = sqrtf(__fadd_rn(__fmul_rn(dx, dx), __fmul_rn(dy, dy)));
    const float ld0 = log10f(d0 + 1.0f);
    const float ldd = log10f(fabsf(sz - lz) + 1.0f);

    const float b  = bsum[li];
    const float la = log_amp[s * NLOCS + tid];
    out[s * NLOCS + tid] = (la - ec * ld0 - dc * ldd - b) / denom;
}

// ---------------- launch ----------------
extern "C" void kernel_launch(void* const* d_in, const int* in_sizes, int n_in,
                              void* d_out, int out_size) {
    const float* src      = (const float*)d_in[0];
    const int*   ind      = (const int*)  d_in[1];
    const float* log_amp  = (const float*)d_in[2];
    const int*   phase    = (const int*)  d_in[3];
    const float* locs     = (const float*)d_in[4];
    const float* grid     = (const float*)d_in[5];
    const float* mag_coef = (const float*)d_in[6];
    const float* eps_coef = (const float*)d_in[7];
    const float* dep_coef = (const float*)d_in[8];
    const float* bias     = (const float*)d_in[9];
    float* out = (float*)d_out;

    dim3 g1(NSRC / 256, NSLICE);
    slice_min_kernel<<<g1, 256>>>(src, grid);

    select_kernel<<<NSRC, 256>>>(src, grid);

    final_kernel<<<NSRC, 512>>>(src, ind, log_amp, phase, locs,
                                mag_coef, eps_coef, dep_coef, bias, out);
}

// round 6
// speedup vs baseline: 2.2284x; 1.1393x over previous
#include <cuda_runtime.h>
#include <math.h>
#include <stdint.h>

#define NSRC   2048
#define NGRID  50000
#define NLOCS  500
#define KTOP   5
#define NSLICE 256
#define SL     196          // ceil(50000/256); last slice has 20 points
#define NPAIR  98           // SL/2
#define SPT    4            // sources per thread in slice_min
#define FINF   __int_as_float(0x7f800000)

// ---------------- device scratch ----------------
__device__ float g_sd[NSRC * NSLICE];      // per (src, slice) min "e"
__device__ int   g_topk[NSRC * KTOP];      // final top-5 grid idx per src

// ---------------- f32x2 packed helpers (sm_103a FFMA2) ----------------
__device__ __forceinline__ unsigned long long pk2(float lo, float hi) {
    unsigned long long r;
    asm("mov.b64 %0, {%1, %2};"
        : "=l"(r) : "r"(__float_as_uint(lo)), "r"(__float_as_uint(hi)));
    return r;
}
__device__ __forceinline__ unsigned long long fma2(unsigned long long a,
                                                   unsigned long long b,
                                                   unsigned long long c) {
    unsigned long long d;
    asm("fma.rn.f32x2 %0, %1, %2, %3;" : "=l"(d) : "l"(a), "l"(b), "l"(c));
    return d;
}
__device__ __forceinline__ void upk2(unsigned long long v, float& lo, float& hi) {
    unsigned int a, b;
    asm("mov.b64 {%0, %1}, %2;" : "=r"(a), "=r"(b) : "l"(v));
    lo = __uint_as_float(a);
    hi = __uint_as_float(b);
}

// ============ kernel 1: per-(src, slice) branchless minimum ============
// grid = (NSRC/(256*SPT), NSLICE) = (2, 256); 256 threads.
// Each thread handles SPT=4 sources; grid points processed in packed pairs
// with fma.rn.f32x2 (per-lane IEEE fma, bit-identical to select's fmaf).
// Ordering key: e = |g|^2 - 2*s.g  (== d2 - |s|^2, same order as ref d2).
__global__ __launch_bounds__(256)
void slice_min_kernel(const float* __restrict__ src,
                      const float* __restrict__ grid) {
    __shared__ float4 tileA[NPAIR];   // (x0, x1, y0, y1)
    __shared__ float4 tileB[NPAIR];   // (z0, z1, w0, w1)

    const int slice = blockIdx.y;
    const int base  = slice * SL;
    const int n     = min(SL, NGRID - base);      // 196 or 20 (even)
    const int npair = (n + 1) >> 1;

    if (threadIdx.x < npair) {
        const int p  = threadIdx.x;
        const int g0 = base + 2 * p;
        const int g1 = g0 + 1;
        float x0 = grid[g0 * 3 + 0] / 1000.0f;
        float y0 = grid[g0 * 3 + 1] / 1000.0f;
        float z0 = grid[g0 * 3 + 2] / 1000.0f;
        float w0 = __fadd_rn(__fadd_rn(__fmul_rn(x0, x0), __fmul_rn(y0, y0)),
                             __fmul_rn(z0, z0));
        float x1 = 1e30f, y1 = 1e30f, z1 = 1e30f, w1 = 1e30f;  // pad -> +inf e
        if (2 * p + 1 < n) {
            x1 = grid[g1 * 3 + 0] / 1000.0f;
            y1 = grid[g1 * 3 + 1] / 1000.0f;
            z1 = grid[g1 * 3 + 2] / 1000.0f;
            w1 = __fadd_rn(__fadd_rn(__fmul_rn(x1, x1), __fmul_rn(y1, y1)),
                           __fmul_rn(z1, z1));
        }
        tileA[p] = make_float4(x0, x1, y0, y1);
        tileB[p] = make_float4(z0, z1, w0, w1);
    }
    __syncthreads();

    const int s0 = blockIdx.x * (256 * SPT) + threadIdx.x;

    unsigned long long mx2[SPT], my2[SPT], mz2[SPT];
#pragma unroll
    for (int k = 0; k < SPT; k++) {
        const int s = s0 + k * 256;
        float mx = -2.0f * (src[s * 3 + 0] / 1000.0f);
        float my = -2.0f * (src[s * 3 + 1] / 1000.0f);
        float mz = -2.0f * (src[s * 3 + 2] / 1000.0f);
        mx2[k] = pk2(mx, mx);
        my2[k] = pk2(my, my);
        mz2[k] = pk2(mz, mz);
    }

    float accL[SPT], accH[SPT];
#pragma unroll
    for (int k = 0; k < SPT; k++) { accL[k] = FINF; accH[k] = FINF; }

#pragma unroll 2
    for (int p = 0; p < npair; p++) {
        float4 A = tileA[p];
        float4 B = tileB[p];
        unsigned long long xx = pk2(A.x, A.y);
        unsigned long long yy = pk2(A.z, A.w);
        unsigned long long zz = pk2(B.x, B.y);
        unsigned long long ww = pk2(B.z, B.w);
#pragma unroll
        for (int k = 0; k < SPT; k++) {
            unsigned long long e = fma2(mz2[k], zz, ww);
            e = fma2(my2[k], yy, e);
            e = fma2(mx2[k], xx, e);
            float lo, hi;
            upk2(e, lo, hi);
            accL[k] = fminf(accL[k], lo);
            accH[k] = fminf(accH[k], hi);
        }
    }

#pragma unroll
    for (int k = 0; k < SPT; k++) {
        const int s = s0 + k * 256;
        g_sd[s * NSLICE + slice] = fminf(accL[k], accH[k]);
    }
}

// ============ kernel 2: exact top-5 per source ============
// block = one source, 256 threads.
//  A) 5 rounds of block-argmin over 256 slice minima -> 5 candidate slices
//     (provably contain the global top-5).
//  B) recompute e for the <=980 candidate points into smem.
//  C) 5 rounds of block-argmin with grid-index tie-break -> g_topk.
__global__ __launch_bounds__(256)
void select_kernel(const float* __restrict__ src,
                   const float* __restrict__ grid) {
    const int s = blockIdx.x;
    const int t = threadIdx.x;
    const int lane = t & 31;
    const int wid  = t >> 5;

    __shared__ float sv[NSLICE];
    __shared__ int   csl[KTOP];
    __shared__ float ev[KTOP * SL];
    __shared__ int   eg[KTOP * SL];
    __shared__ float wv[8];
    __shared__ int   wj[8];
    __shared__ int   win_g;

    sv[t] = g_sd[s * NSLICE + t];
    __syncthreads();

    // ---- stage A: 5 smallest slice minima (tie -> lower slice id) ----
    for (int r = 0; r < KTOP; r++) {
        float v = sv[t];
        int   j = t;
#pragma unroll
        for (int off = 16; off > 0; off >>= 1) {
            float ov = __shfl_xor_sync(0xffffffffu, v, off);
            int   oj = __shfl_xor_sync(0xffffffffu, j, off);
            if (ov < v || (ov == v && oj < j)) { v = ov; j = oj; }
        }
        if (lane == 0) { wv[wid] = v; wj[wid] = j; }
        __syncthreads();
        if (t < 8) {
            float v2 = wv[t];
            int   j2 = wj[t];
#pragma unroll
            for (int off = 4; off > 0; off >>= 1) {
                float ov = __shfl_xor_sync(0x000000ffu, v2, off);
                int   oj = __shfl_xor_sync(0x000000ffu, j2, off);
                if (ov < v2 || (ov == v2 && oj < j2)) { v2 = ov; j2 = oj; }
            }
            if (t == 0) { csl[r] = j2; sv[j2] = FINF; }
        }
        __syncthreads();
    }

    // ---- stage B: candidate e values ----
    const float mx = -2.0f * (src[s * 3 + 0] / 1000.0f);
    const float my = -2.0f * (src[s * 3 + 1] / 1000.0f);
    const float mz = -2.0f * (src[s * 3 + 2] / 1000.0f);

    if (t < SL) {
#pragma unroll
        for (int k = 0; k < KTOP; k++) {
            int gi = csl[k] * SL + t;
            float e = FINF;
            if (gi < NGRID) {
                float x = grid[gi * 3 + 0] / 1000.0f;
                float y = grid[gi * 3 + 1] / 1000.0f;
                float z = grid[gi * 3 + 2] / 1000.0f;
                float n2 = __fadd_rn(__fadd_rn(__fmul_rn(x, x),
                                               __fmul_rn(y, y)),
                                     __fmul_rn(z, z));
                e = fmaf(mx, x, fmaf(my, y, fmaf(mz, z, n2)));
            }
            ev[k * SL + t] = e;
            eg[k * SL + t] = gi;
        }
    }
    __syncthreads();

    // ---- stage C: 5 rounds argmin over 980 (tie -> lower grid idx) ----
    const int TOT = KTOP * SL;
    for (int r = 0; r < KTOP; r++) {
        float bv = FINF;
        int   bg = 0x7fffffff;
        for (int p = t; p < TOT; p += 256) {
            float v = ev[p];
            int   g = eg[p];
            if (v < bv || (v == bv && g < bg)) { bv = v; bg = g; }
        }
#pragma unroll
        for (int off = 16; off > 0; off >>= 1) {
            float ov = __shfl_xor_sync(0xffffffffu, bv, off);
            int   og = __shfl_xor_sync(0xffffffffu, bg, off);
            if (ov < bv || (ov == bv && og < bg)) { bv = ov; bg = og; }
        }
        if (lane == 0) { wv[wid] = bv; wj[wid] = bg; }
        __syncthreads();
        if (t < 8) {
            float v2 = wv[t];
            int   g2 = wj[t];
#pragma unroll
            for (int off = 4; off > 0; off >>= 1) {
                float ov = __shfl_xor_sync(0x000000ffu, v2, off);
                int   og = __shfl_xor_sync(0x000000ffu, g2, off);
                if (ov < v2 || (ov == v2 && og < g2)) { v2 = ov; g2 = og; }
            }
            if (t == 0) { g_topk[s * KTOP + r] = g2; win_g = g2; }
        }
        __syncthreads();
        for (int p = t; p < TOT; p += 256)
            if (eg[p] == win_g) ev[p] = FINF;   // grid idx unique across slices
        __syncthreads();
    }
}

// ============ kernel 3: bias rowsum + epilogue ============
__global__ __launch_bounds__(512)
void final_kernel(const float* __restrict__ src,
                  const int*   __restrict__ ind,
                  const float* __restrict__ log_amp,
                  const int*   __restrict__ phase,
                  const float* __restrict__ locs,
                  const float* __restrict__ mag_coef,
                  const float* __restrict__ eps_coef,
                  const float* __restrict__ dep_coef,
                  const float* __restrict__ bias,
                  float*       __restrict__ out) {
    const int s   = blockIdx.x;
    const int tid = threadIdx.x;

    __shared__ int   tk[KTOP];
    __shared__ float bsum[NLOCS];

    if (tid < KTOP) tk[tid] = g_topk[s * KTOP + tid];
    __syncthreads();

    const int ph = phase[0];

    if (tid < NLOCS) {
        float acc = 0.0f;
#pragma unroll
        for (int k = 0; k < KTOP; k++) {
            const float2* row =
                (const float2*)(bias + (size_t)tk[k] * (NLOCS * 2));
            float2 v = __ldg(&row[tid]);
            acc += ph ? v.y : v.x;
        }
        bsum[tid] = acc / 5.0f;
    }
    __syncthreads();

    if (tid >= NLOCS) return;

    const float ec    = eps_coef[ph];
    const float dc    = dep_coef[ph];
    const float denom = fmaxf(mag_coef[ph], 1e-12f);

    const float sx = src[s * 3 + 0];
    const float sy = src[s * 3 + 1];
    const float sz = src[s * 3 + 2];

    const int li = ind[tid];
    const float lx = locs[li * 3 + 0];
    const float ly = locs[li * 3 + 1];
    const float lz = locs[li * 3 + 2];

    const float dx = sx - lx;
    const float dy = sy - ly;
    const float d0  = sqrtf(__fadd_rn(__fmul_rn(dx, dx), __fmul_rn(dy, dy)));
    const float ld0 = log10f(d0 + 1.0f);
    const float ldd = log10f(fabsf(sz - lz) + 1.0f);

    const float b  = bsum[li];
    const float la = log_amp[s * NLOCS + tid];
    out[s * NLOCS + tid] = (la - ec * ld0 - dc * ldd - b) / denom;
}

// ---------------- launch ----------------
extern "C" void kernel_launch(void* const* d_in, const int* in_sizes, int n_in,
                              void* d_out, int out_size) {
    const float* src      = (const float*)d_in[0];
    const int*   ind      = (const int*)  d_in[1];
    const float* log_amp  = (const float*)d_in[2];
    const int*   phase    = (const int*)  d_in[3];
    const float* locs     = (const float*)d_in[4];
    const float* grid     = (const float*)d_in[5];
    const float* mag_coef = (const float*)d_in[6];
    const float* eps_coef = (const float*)d_in[7];
    const float* dep_coef = (const float*)d_in[8];
    const float* bias     = (const float*)d_in[9];
    float* out = (float*)d_out;

    dim3 g1(NSRC / (256 * SPT), NSLICE);
    slice_min_kernel<<<g1, 256>>>(src, grid);

    select_kernel<<<NSRC, 256>>>(src, grid);

    final_kernel<<<NSRC, 512>>>(src, ind, log_amp, phase, locs,
                                mag_coef, eps_coef, dep_coef, bias, out);
}

// round 7
// speedup vs baseline: 2.2308x; 1.0011x over previous
#include <cuda_runtime.h>
#include <math.h>
#include <stdint.h>

#define NSRC   2048
#define NGRID  50000
#define NLOCS  500
#define KTOP   5
#define NSLICE 256
#define SL     196          // ceil(50000/256); last slice has 20 points
#define NPAIR  98           // SL/2
#define SPT    2            // sources per thread in slice_min
#define FINF   __int_as_float(0x7f800000)

// ---------------- device scratch ----------------
__device__ float g_sd[NSRC * NSLICE];      // per (src, slice) min "e"
__device__ int   g_topk[NSRC * KTOP];      // final top-5 grid idx per src
__device__ float g_bsum[NSRC * NLOCS];     // per (src, station) bias mean

// ---------------- f32x2 packed helpers (sm_103a FFMA2) ----------------
__device__ __forceinline__ unsigned long long pk2(float lo, float hi) {
    unsigned long long r;
    asm("mov.b64 %0, {%1, %2};"
        : "=l"(r) : "r"(__float_as_uint(lo)), "r"(__float_as_uint(hi)));
    return r;
}
__device__ __forceinline__ unsigned long long fma2(unsigned long long a,
                                                   unsigned long long b,
                                                   unsigned long long c) {
    unsigned long long d;
    asm("fma.rn.f32x2 %0, %1, %2, %3;" : "=l"(d) : "l"(a), "l"(b), "l"(c));
    return d;
}
__device__ __forceinline__ void upk2(unsigned long long v, float& lo, float& hi) {
    unsigned int a, b;
    asm("mov.b64 {%0, %1}, %2;" : "=r"(a), "=r"(b) : "l"(v));
    lo = __uint_as_float(a);
    hi = __uint_as_float(b);
}
__device__ __forceinline__ float fsqrt_approx(float x) {
    float r;
    asm("sqrt.approx.f32 %0, %1;" : "=f"(r) : "f"(x));
    return r;
}

// ============ kernel 1: per-(src, slice) branchless minimum ============
// grid = (NSRC/(256*SPT), NSLICE) = (4, 256); 256 threads.
// Each thread handles SPT=2 sources; grid points processed in packed pairs
// with fma.rn.f32x2 (per-lane IEEE fma, bit-identical to select's fmaf).
// Ordering key: e = |g|^2 - 2*s.g  (== d2 - |s|^2, same order as ref d2).
__global__ __launch_bounds__(256)
void slice_min_kernel(const float* __restrict__ src,
                      const float* __restrict__ grid) {
    __shared__ float4 tileA[NPAIR];   // (x0, x1, y0, y1)
    __shared__ float4 tileB[NPAIR];   // (z0, z1, w0, w1)

    const int slice = blockIdx.y;
    const int base  = slice * SL;
    const int n     = min(SL, NGRID - base);      // 196 or 20
    const int npair = (n + 1) >> 1;

    if (threadIdx.x < npair) {
        const int p  = threadIdx.x;
        const int g0 = base + 2 * p;
        const int g1 = g0 + 1;
        float x0 = grid[g0 * 3 + 0] / 1000.0f;
        float y0 = grid[g0 * 3 + 1] / 1000.0f;
        float z0 = grid[g0 * 3 + 2] / 1000.0f;
        float w0 = __fadd_rn(__fadd_rn(__fmul_rn(x0, x0), __fmul_rn(y0, y0)),
                             __fmul_rn(z0, z0));
        float x1 = 1e30f, y1 = 1e30f, z1 = 1e30f, w1 = 1e30f;  // pad -> huge e
        if (2 * p + 1 < n) {
            x1 = grid[g1 * 3 + 0] / 1000.0f;
            y1 = grid[g1 * 3 + 1] / 1000.0f;
            z1 = grid[g1 * 3 + 2] / 1000.0f;
            w1 = __fadd_rn(__fadd_rn(__fmul_rn(x1, x1), __fmul_rn(y1, y1)),
                           __fmul_rn(z1, z1));
        }
        tileA[p] = make_float4(x0, x1, y0, y1);
        tileB[p] = make_float4(z0, z1, w0, w1);
    }
    __syncthreads();

    const int s0 = blockIdx.x * (256 * SPT) + threadIdx.x;

    unsigned long long mx2[SPT], my2[SPT], mz2[SPT];
#pragma unroll
    for (int k = 0; k < SPT; k++) {
        const int s = s0 + k * 256;
        float mx = -2.0f * (src[s * 3 + 0] / 1000.0f);
        float my = -2.0f * (src[s * 3 + 1] / 1000.0f);
        float mz = -2.0f * (src[s * 3 + 2] / 1000.0f);
        mx2[k] = pk2(mx, mx);
        my2[k] = pk2(my, my);
        mz2[k] = pk2(mz, mz);
    }

    float accL[SPT], accH[SPT];
#pragma unroll
    for (int k = 0; k < SPT; k++) { accL[k] = FINF; accH[k] = FINF; }

#pragma unroll 2
    for (int p = 0; p < npair; p++) {
        float4 A = tileA[p];
        float4 B = tileB[p];
        unsigned long long xx = pk2(A.x, A.y);
        unsigned long long yy = pk2(A.z, A.w);
        unsigned long long zz = pk2(B.x, B.y);
        unsigned long long ww = pk2(B.z, B.w);
#pragma unroll
        for (int k = 0; k < SPT; k++) {
            unsigned long long e = fma2(mz2[k], zz, ww);
            e = fma2(my2[k], yy, e);
            e = fma2(mx2[k], xx, e);
            float lo, hi;
            upk2(e, lo, hi);
            accL[k] = fminf(accL[k], lo);
            accH[k] = fminf(accH[k], hi);
        }
    }

#pragma unroll
    for (int k = 0; k < SPT; k++) {
        const int s = s0 + k * 256;
        g_sd[s * NSLICE + slice] = fminf(accL[k], accH[k]);
    }
}

// ============ kernel 2: exact top-5 per source ============
// block = one source, 256 threads.
//  A) 5 rounds of block-argmin over 256 slice minima -> 5 candidate slices
//     (provably contain the global top-5).
//  B) recompute e for the <=980 candidate points into smem.
//  C) 5 rounds of block-argmin with grid-index tie-break -> g_topk.
__global__ __launch_bounds__(256)
void select_kernel(const float* __restrict__ src,
                   const float* __restrict__ grid) {
    const int s = blockIdx.x;
    const int t = threadIdx.x;
    const int lane = t & 31;
    const int wid  = t >> 5;

    __shared__ float sv[NSLICE];
    __shared__ int   csl[KTOP];
    __shared__ float ev[KTOP * SL];
    __shared__ int   eg[KTOP * SL];
    __shared__ float wv[8];
    __shared__ int   wj[8];
    __shared__ int   win_g;

    sv[t] = g_sd[s * NSLICE + t];
    __syncthreads();

    // ---- stage A: 5 smallest slice minima (tie -> lower slice id) ----
    for (int r = 0; r < KTOP; r++) {
        float v = sv[t];
        int   j = t;
#pragma unroll
        for (int off = 16; off > 0; off >>= 1) {
            float ov = __shfl_xor_sync(0xffffffffu, v, off);
            int   oj = __shfl_xor_sync(0xffffffffu, j, off);
            if (ov < v || (ov == v && oj < j)) { v = ov; j = oj; }
        }
        if (lane == 0) { wv[wid] = v; wj[wid] = j; }
        __syncthreads();
        if (t < 8) {
            float v2 = wv[t];
            int   j2 = wj[t];
#pragma unroll
            for (int off = 4; off > 0; off >>= 1) {
                float ov = __shfl_xor_sync(0x000000ffu, v2, off);
                int   oj = __shfl_xor_sync(0x000000ffu, j2, off);
                if (ov < v2 || (ov == v2 && oj < j2)) { v2 = ov; j2 = oj; }
            }
            if (t == 0) { csl[r] = j2; sv[j2] = FINF; }
        }
        __syncthreads();
    }

    // ---- stage B: candidate e values ----
    const float mx = -2.0f * (src[s * 3 + 0] / 1000.0f);
    const float my = -2.0f * (src[s * 3 + 1] / 1000.0f);
    const float mz = -2.0f * (src[s * 3 + 2] / 1000.0f);

    if (t < SL) {
#pragma unroll
        for (int k = 0; k < KTOP; k++) {
            int gi = csl[k] * SL + t;
            float e = FINF;
            if (gi < NGRID) {
                float x = grid[gi * 3 + 0] / 1000.0f;
                float y = grid[gi * 3 + 1] / 1000.0f;
                float z = grid[gi * 3 + 2] / 1000.0f;
                float n2 = __fadd_rn(__fadd_rn(__fmul_rn(x, x),
                                               __fmul_rn(y, y)),
                                     __fmul_rn(z, z));
                e = fmaf(mx, x, fmaf(my, y, fmaf(mz, z, n2)));
            }
            ev[k * SL + t] = e;
            eg[k * SL + t] = gi;
        }
    }
    __syncthreads();

    // ---- stage C: 5 rounds argmin over 980 (tie -> lower grid idx) ----
    const int TOT = KTOP * SL;
    for (int r = 0; r < KTOP; r++) {
        float bv = FINF;
        int   bg = 0x7fffffff;
        for (int p = t; p < TOT; p += 256) {
            float v = ev[p];
            int   g = eg[p];
            if (v < bv || (v == bv && g < bg)) { bv = v; bg = g; }
        }
#pragma unroll
        for (int off = 16; off > 0; off >>= 1) {
            float ov = __shfl_xor_sync(0xffffffffu, bv, off);
            int   og = __shfl_xor_sync(0xffffffffu, bg, off);
            if (ov < bv || (ov == bv && og < bg)) { bv = ov; bg = og; }
        }
        if (lane == 0) { wv[wid] = bv; wj[wid] = bg; }
        __syncthreads();
        if (t < 8) {
            float v2 = wv[t];
            int   g2 = wj[t];
#pragma unroll
            for (int off = 4; off > 0; off >>= 1) {
                float ov = __shfl_xor_sync(0x000000ffu, v2, off);
                int   og = __shfl_xor_sync(0x000000ffu, g2, off);
                if (ov < v2 || (ov == v2 && og < g2)) { v2 = ov; g2 = og; }
            }
            if (t == 0) { g_topk[s * KTOP + r] = g2; win_g = g2; }
        }
        __syncthreads();
        for (int p = t; p < TOT; p += 256)
            if (eg[p] == win_g) ev[p] = FINF;   // grid idx unique across slices
        __syncthreads();
    }
}

// ============ kernel 3: per-(src, station) bias mean — barrier-free ========
// block = one source, 512 threads (500 active); thread j streams
// bias[tk[k], j, ph] for k=0..4 (stride-8B, sector-coalesced) -> g_bsum.
__global__ __launch_bounds__(512)
void bias_sum_kernel(const int* __restrict__ phase,
                     const float* __restrict__ bias) {
    const int s = blockIdx.x;
    const int j = threadIdx.x;
    if (j >= NLOCS) return;

    const int ph = phase[0];
    const int t0 = g_topk[s * KTOP + 0];
    const int t1 = g_topk[s * KTOP + 1];
    const int t2 = g_topk[s * KTOP + 2];
    const int t3 = g_topk[s * KTOP + 3];
    const int t4 = g_topk[s * KTOP + 4];

    const int col = j * 2 + ph;
    float acc = __ldg(&bias[(size_t)t0 * (NLOCS * 2) + col]);
    acc += __ldg(&bias[(size_t)t1 * (NLOCS * 2) + col]);
    acc += __ldg(&bias[(size_t)t2 * (NLOCS * 2) + col]);
    acc += __ldg(&bias[(size_t)t3 * (NLOCS * 2) + col]);
    acc += __ldg(&bias[(size_t)t4 * (NLOCS * 2) + col]);
    g_bsum[s * NLOCS + j] = acc / 5.0f;
}

// ============ kernel 4: epilogue — barrier-free ============
__global__ __launch_bounds__(512)
void epilogue_kernel(const float* __restrict__ src,
                     const int*   __restrict__ ind,
                     const float* __restrict__ log_amp,
                     const int*   __restrict__ phase,
                     const float* __restrict__ locs,
                     const float* __restrict__ mag_coef,
                     const float* __restrict__ eps_coef,
                     const float* __restrict__ dep_coef,
                     float*       __restrict__ out) {
    const int s = blockIdx.x;
    const int t = threadIdx.x;
    if (t >= NLOCS) return;

    const int ph = phase[0];
    const float ec    = eps_coef[ph];
    const float dc    = dep_coef[ph];
    const float denom = fmaxf(mag_coef[ph], 1e-12f);

    const float sx = src[s * 3 + 0];
    const float sy = src[s * 3 + 1];
    const float sz = src[s * 3 + 2];

    const int li = ind[t];
    const float lx = locs[li * 3 + 0];
    const float ly = locs[li * 3 + 1];
    const float lz = locs[li * 3 + 2];

    const float dx = sx - lx;
    const float dy = sy - ly;
    const float d0  = fsqrt_approx(__fadd_rn(__fmul_rn(dx, dx),
                                             __fmul_rn(dy, dy)));
    const float ld0 = __log10f(d0 + 1.0f);
    const float ldd = __log10f(fabsf(sz - lz) + 1.0f);

    const float b  = g_bsum[s * NLOCS + li];
    const float la = log_amp[s * NLOCS + t];
    out[s * NLOCS + t] = (la - ec * ld0 - dc * ldd - b) / denom;
}

// ---------------- launch ----------------
extern "C" void kernel_launch(void* const* d_in, const int* in_sizes, int n_in,
                              void* d_out, int out_size) {
    const float* src      = (const float*)d_in[0];
    const int*   ind      = (const int*)  d_in[1];
    const float* log_amp  = (const float*)d_in[2];
    const int*   phase    = (const int*)  d_in[3];
    const float* locs     = (const float*)d_in[4];
    const float* grid     = (const float*)d_in[5];
    const float* mag_coef = (const float*)d_in[6];
    const float* eps_coef = (const float*)d_in[7];
    const float* dep_coef = (const float*)d_in[8];
    const float* bias     = (const float*)d_in[9];
    float* out = (float*)d_out;

    dim3 g1(NSRC / (256 * SPT), NSLICE);
    slice_min_kernel<<<g1, 256>>>(src, grid);

    select_kernel<<<NSRC, 256>>>(src, grid);

    bias_sum_kernel<<<NSRC, 512>>>(phase, bias);

    epilogue_kernel<<<NSRC, 512>>>(src, ind, log_amp, phase, locs,
                                   mag_coef, eps_coef, dep_coef, out);
}

// round 8
// speedup vs baseline: 2.4828x; 1.1130x over previous
#include <cuda_runtime.h>
#include <math.h>
#include <stdint.h>

#define NSRC   2048
#define NGRID  50000
#define NLOCS  500
#define KTOP   5
#define NSLICE 256
#define SL     196          // ceil(50000/256); last slice has 20 points
#define NPAIR  98           // SL/2
#define SPT    4            // sources per thread in slice_min
#define SMT    128          // threads in slice_min
#define FINF   __int_as_float(0x7f800000)

// ---------------- device scratch ----------------
__device__ float g_sd[NSRC * NSLICE];      // per (src, slice) min "e"
__device__ int   g_topk[NSRC * KTOP];      // final top-5 grid idx per src

// ---------------- f32x2 packed helpers (sm_103a FFMA2) ----------------
__device__ __forceinline__ unsigned long long pk2(float lo, float hi) {
    unsigned long long r;
    asm("mov.b64 %0, {%1, %2};"
        : "=l"(r) : "r"(__float_as_uint(lo)), "r"(__float_as_uint(hi)));
    return r;
}
__device__ __forceinline__ unsigned long long fma2(unsigned long long a,
                                                   unsigned long long b,
                                                   unsigned long long c) {
    unsigned long long d;
    asm("fma.rn.f32x2 %0, %1, %2, %3;" : "=l"(d) : "l"(a), "l"(b), "l"(c));
    return d;
}
__device__ __forceinline__ void upk2(unsigned long long v, float& lo, float& hi) {
    unsigned int a, b;
    asm("mov.b64 {%0, %1}, %2;" : "=r"(a), "=r"(b) : "l"(v));
    lo = __uint_as_float(a);
    hi = __uint_as_float(b);
}
__device__ __forceinline__ float fsqrt_approx(float x) {
    float r;
    asm("sqrt.approx.f32 %0, %1;" : "=f"(r) : "f"(x));
    return r;
}

// ============ kernel 1: per-(src, slice) branchless minimum ============
// grid = (NSRC/(SMT*SPT), NSLICE) = (4, 256); 128 threads; SPT=4 sources
// per thread (cheap inner loop) with 1024 blocks for occupancy (~44%).
// Grid points processed in packed pairs with fma.rn.f32x2 (per-lane IEEE
// fma, bit-identical to select's fmaf).
// Ordering key: e = |g|^2 - 2*s.g  (== d2 - |s|^2, same order as ref d2).
__global__ __launch_bounds__(SMT)
void slice_min_kernel(const float* __restrict__ src,
                      const float* __restrict__ grid) {
    __shared__ float4 tileA[NPAIR];   // (x0, x1, y0, y1)
    __shared__ float4 tileB[NPAIR];   // (z0, z1, w0, w1)

    const int slice = blockIdx.y;
    const int base  = slice * SL;
    const int n     = min(SL, NGRID - base);      // 196 or 20
    const int npair = (n + 1) >> 1;

    if (threadIdx.x < npair) {
        const int p  = threadIdx.x;
        const int g0 = base + 2 * p;
        const int g1 = g0 + 1;
        float x0 = grid[g0 * 3 + 0] / 1000.0f;
        float y0 = grid[g0 * 3 + 1] / 1000.0f;
        float z0 = grid[g0 * 3 + 2] / 1000.0f;
        float w0 = __fadd_rn(__fadd_rn(__fmul_rn(x0, x0), __fmul_rn(y0, y0)),
                             __fmul_rn(z0, z0));
        float x1 = 1e30f, y1 = 1e30f, z1 = 1e30f, w1 = 1e30f;  // pad -> huge e
        if (2 * p + 1 < n) {
            x1 = grid[g1 * 3 + 0] / 1000.0f;
            y1 = grid[g1 * 3 + 1] / 1000.0f;
            z1 = grid[g1 * 3 + 2] / 1000.0f;
            w1 = __fadd_rn(__fadd_rn(__fmul_rn(x1, x1), __fmul_rn(y1, y1)),
                           __fmul_rn(z1, z1));
        }
        tileA[p] = make_float4(x0, x1, y0, y1);
        tileB[p] = make_float4(z0, z1, w0, w1);
    }
    __syncthreads();

    const int s0 = blockIdx.x * (SMT * SPT) + threadIdx.x;

    unsigned long long mx2[SPT], my2[SPT], mz2[SPT];
#pragma unroll
    for (int k = 0; k < SPT; k++) {
        const int s = s0 + k * SMT;
        float mx = -2.0f * (src[s * 3 + 0] / 1000.0f);
        float my = -2.0f * (src[s * 3 + 1] / 1000.0f);
        float mz = -2.0f * (src[s * 3 + 2] / 1000.0f);
        mx2[k] = pk2(mx, mx);
        my2[k] = pk2(my, my);
        mz2[k] = pk2(mz, mz);
    }

    float accL[SPT], accH[SPT];
#pragma unroll
    for (int k = 0; k < SPT; k++) { accL[k] = FINF; accH[k] = FINF; }

#pragma unroll 2
    for (int p = 0; p < npair; p++) {
        float4 A = tileA[p];
        float4 B = tileB[p];
        unsigned long long xx = pk2(A.x, A.y);
        unsigned long long yy = pk2(A.z, A.w);
        unsigned long long zz = pk2(B.x, B.y);
        unsigned long long ww = pk2(B.z, B.w);
#pragma unroll
        for (int k = 0; k < SPT; k++) {
            unsigned long long e = fma2(mz2[k], zz, ww);
            e = fma2(my2[k], yy, e);
            e = fma2(mx2[k], xx, e);
            float lo, hi;
            upk2(e, lo, hi);
            accL[k] = fminf(accL[k], lo);
            accH[k] = fminf(accH[k], hi);
        }
    }

#pragma unroll
    for (int k = 0; k < SPT; k++) {
        const int s = s0 + k * SMT;
        g_sd[s * NSLICE + slice] = fminf(accL[k], accH[k]);
    }
}

// ============ kernel 2: exact top-5 per source ============
// block = one source, 256 threads.
//  A) 5 rounds of block-argmin over 256 slice minima -> 5 candidate slices
//     (provably contain the global top-5).
//  B) recompute e for the <=980 candidate points into smem.
//  C) 5 rounds of block-argmin with grid-index tie-break -> g_topk.
__global__ __launch_bounds__(256)
void select_kernel(const float* __restrict__ src,
                   const float* __restrict__ grid) {
    const int s = blockIdx.x;
    const int t = threadIdx.x;
    const int lane = t & 31;
    const int wid  = t >> 5;

    __shared__ float sv[NSLICE];
    __shared__ int   csl[KTOP];
    __shared__ float ev[KTOP * SL];
    __shared__ int   eg[KTOP * SL];
    __shared__ float wv[8];
    __shared__ int   wj[8];
    __shared__ int   win_g;

    sv[t] = g_sd[s * NSLICE + t];
    __syncthreads();

    // ---- stage A: 5 smallest slice minima (tie -> lower slice id) ----
    for (int r = 0; r < KTOP; r++) {
        float v = sv[t];
        int   j = t;
#pragma unroll
        for (int off = 16; off > 0; off >>= 1) {
            float ov = __shfl_xor_sync(0xffffffffu, v, off);
            int   oj = __shfl_xor_sync(0xffffffffu, j, off);
            if (ov < v || (ov == v && oj < j)) { v = ov; j = oj; }
        }
        if (lane == 0) { wv[wid] = v; wj[wid] = j; }
        __syncthreads();
        if (t < 8) {
            float v2 = wv[t];
            int   j2 = wj[t];
#pragma unroll
            for (int off = 4; off > 0; off >>= 1) {
                float ov = __shfl_xor_sync(0x000000ffu, v2, off);
                int   oj = __shfl_xor_sync(0x000000ffu, j2, off);
                if (ov < v2 || (ov == v2 && oj < j2)) { v2 = ov; j2 = oj; }
            }
            if (t == 0) { csl[r] = j2; sv[j2] = FINF; }
        }
        __syncthreads();
    }

    // ---- stage B: candidate e values ----
    const float mx = -2.0f * (src[s * 3 + 0] / 1000.0f);
    const float my = -2.0f * (src[s * 3 + 1] / 1000.0f);
    const float mz = -2.0f * (src[s * 3 + 2] / 1000.0f);

    if (t < SL) {
#pragma unroll
        for (int k = 0; k < KTOP; k++) {
            int gi = csl[k] * SL + t;
            float e = FINF;
            if (gi < NGRID) {
                float x = grid[gi * 3 + 0] / 1000.0f;
                float y = grid[gi * 3 + 1] / 1000.0f;
                float z = grid[gi * 3 + 2] / 1000.0f;
                float n2 = __fadd_rn(__fadd_rn(__fmul_rn(x, x),
                                               __fmul_rn(y, y)),
                                     __fmul_rn(z, z));
                e = fmaf(mx, x, fmaf(my, y, fmaf(mz, z, n2)));
            }
            ev[k * SL + t] = e;
            eg[k * SL + t] = gi;
        }
    }
    __syncthreads();

    // ---- stage C: 5 rounds argmin over 980 (tie -> lower grid idx) ----
    const int TOT = KTOP * SL;
    for (int r = 0; r < KTOP; r++) {
        float bv = FINF;
        int   bg = 0x7fffffff;
        for (int p = t; p < TOT; p += 256) {
            float v = ev[p];
            int   g = eg[p];
            if (v < bv || (v == bv && g < bg)) { bv = v; bg = g; }
        }
#pragma unroll
        for (int off = 16; off > 0; off >>= 1) {
            float ov = __shfl_xor_sync(0xffffffffu, bv, off);
            int   og = __shfl_xor_sync(0xffffffffu, bg, off);
            if (ov < bv || (ov == bv && og < bg)) { bv = ov; bg = og; }
        }
        if (lane == 0) { wv[wid] = bv; wj[wid] = bg; }
        __syncthreads();
        if (t < 8) {
            float v2 = wv[t];
            int   g2 = wj[t];
#pragma unroll
            for (int off = 4; off > 0; off >>= 1) {
                float ov = __shfl_xor_sync(0x000000ffu, v2, off);
                int   og = __shfl_xor_sync(0x000000ffu, g2, off);
                if (ov < v2 || (ov == v2 && og < g2)) { v2 = ov; g2 = og; }
            }
            if (t == 0) { g_topk[s * KTOP + r] = g2; win_g = g2; }
        }
        __syncthreads();
        for (int p = t; p < TOT; p += 256)
            if (eg[p] == win_g) ev[p] = FINF;   // grid idx unique across slices
        __syncthreads();
    }
}

// ============ kernel 3: fused tail — 4 sources per block ============
// 512 blocks x 512 threads.
//  stage 1: 2000 (source, station) bias-mean tasks; consecutive tids map to
//           consecutive stations -> coalesced 8B-stride row streams, 20
//           independent rows in flight per block.
//  stage 2: each thread emits 4 outputs (one per source) at station t;
//           ind/locs loads amortized 4x, 4 independent gather chains.
__global__ __launch_bounds__(512)
void tail_kernel(const float* __restrict__ src,
                 const int*   __restrict__ ind,
                 const float* __restrict__ log_amp,
                 const int*   __restrict__ phase,
                 const float* __restrict__ locs,
                 const float* __restrict__ mag_coef,
                 const float* __restrict__ eps_coef,
                 const float* __restrict__ dep_coef,
                 const float* __restrict__ bias,
                 float*       __restrict__ out) {
    const int s0  = blockIdx.x * 4;
    const int tid = threadIdx.x;

    __shared__ float bsum[4][NLOCS];
    __shared__ int   tks[4 * KTOP];

    if (tid < 4 * KTOP) tks[tid] = g_topk[s0 * KTOP + tid];
    __syncthreads();

    const int ph = phase[0];

    // ---- stage 1: bias means for 4 sources ----
    for (int task = tid; task < 4 * NLOCS; task += 512) {
        const int ss = task / NLOCS;
        const int j  = task - ss * NLOCS;
        const int col = j * 2 + ph;
        float acc = __ldg(&bias[(size_t)tks[ss * KTOP + 0] * (NLOCS * 2) + col]);
        acc += __ldg(&bias[(size_t)tks[ss * KTOP + 1] * (NLOCS * 2) + col]);
        acc += __ldg(&bias[(size_t)tks[ss * KTOP + 2] * (NLOCS * 2) + col]);
        acc += __ldg(&bias[(size_t)tks[ss * KTOP + 3] * (NLOCS * 2) + col]);
        acc += __ldg(&bias[(size_t)tks[ss * KTOP + 4] * (NLOCS * 2) + col]);
        bsum[ss][j] = acc / 5.0f;
    }
    __syncthreads();

    // ---- stage 2: epilogue, 4 outputs per thread ----
    if (tid >= NLOCS) return;

    const float ec    = eps_coef[ph];
    const float dc    = dep_coef[ph];
    const float denom = fmaxf(mag_coef[ph], 1e-12f);

    const int li = ind[tid];
    const float lx = locs[li * 3 + 0];
    const float ly = locs[li * 3 + 1];
    const float lz = locs[li * 3 + 2];

#pragma unroll
    for (int ss = 0; ss < 4; ss++) {
        const int s = s0 + ss;
        const float sx = src[s * 3 + 0];
        const float sy = src[s * 3 + 1];
        const float sz = src[s * 3 + 2];

        const float dx = sx - lx;
        const float dy = sy - ly;
        const float d0  = fsqrt_approx(__fadd_rn(__fmul_rn(dx, dx),
                                                 __fmul_rn(dy, dy)));
        const float ld0 = __log10f(d0 + 1.0f);
        const float ldd = __log10f(fabsf(sz - lz) + 1.0f);

        const float b  = bsum[ss][li];
        const float la = log_amp[s * NLOCS + tid];
        out[s * NLOCS + tid] = (la - ec * ld0 - dc * ldd - b) / denom;
    }
}

// ---------------- launch ----------------
extern "C" void kernel_launch(void* const* d_in, const int* in_sizes, int n_in,
                              void* d_out, int out_size) {
    const float* src      = (const float*)d_in[0];
    const int*   ind      = (const int*)  d_in[1];
    const float* log_amp  = (const float*)d_in[2];
    const int*   phase    = (const int*)  d_in[3];
    const float* locs     = (const float*)d_in[4];
    const float* grid     = (const float*)d_in[5];
    const float* mag_coef = (const float*)d_in[6];
    const float* eps_coef = (const float*)d_in[7];
    const float* dep_coef = (const float*)d_in[8];
    const float* bias     = (const float*)d_in[9];
    float* out = (float*)d_out;

    dim3 g1(NSRC / (SMT * SPT), NSLICE);
    slice_min_kernel<<<g1, SMT>>>(src, grid);

    select_kernel<<<NSRC, 256>>>(src, grid);

    tail_kernel<<<NSRC / 4, 512>>>(src, ind, log_amp, phase, locs,
                                   mag_coef, eps_coef, dep_coef, bias, out);
}